// round 17
// baseline (speedup 1.0000x reference)
#include <cuda_runtime.h>
#include <cuda_bf16.h>
#include <cstdint>

#define B_TOT 1024
#define NW 64

__device__ float g_bm[NW * 8 * 128 * 128];      // bias+mask TRANSPOSED [w][h][j][n] (32MB)
// packed weight fragments: [tile][ks][lane]
__device__ uint4 g_Pc_hm[48 * 8 * 32];          // qkv W^T: {h pair0, h pair1, m pair0, m pair1}
__device__ uint2 g_Pc_l[48 * 8 * 32];           // qkv W^T: l split
__device__ uint4 g_Pp_hm[16 * 8 * 32];          // proj W^T: h+m packed

__device__ __forceinline__ unsigned short bfb(__nv_bfloat16 h) { return *reinterpret_cast<unsigned short*>(&h); }

__device__ __forceinline__ void split3s(float v, unsigned short& h, unsigned short& m, unsigned short& l) {
    __nv_bfloat16 bh = __float2bfloat16(v);
    float r1 = v - __bfloat162float(bh);
    __nv_bfloat16 bm = __float2bfloat16(r1);
    float r2 = r1 - __bfloat162float(bm);
    h = bfb(bh); m = bfb(bm); l = bfb(__float2bfloat16(r2));
}
__device__ __forceinline__ void split2s(float v, unsigned short& h, unsigned short& m) {
    __nv_bfloat16 bh = __float2bfloat16(v);
    float r1 = v - __bfloat162float(bh);
    h = bfb(bh); m = bfb(__float2bfloat16(r1));
}

__device__ __forceinline__ void hmma(float* d, const uint32_t* a, const uint32_t* b) {
    asm volatile("mma.sync.aligned.m16n8k16.row.col.f32.bf16.bf16.f32 "
                 "{%0,%1,%2,%3},{%4,%5,%6,%7},{%8,%9},{%0,%1,%2,%3};"
                 : "+f"(d[0]), "+f"(d[1]), "+f"(d[2]), "+f"(d[3])
                 : "r"(a[0]), "r"(a[1]), "r"(a[2]), "r"(a[3]), "r"(b[0]), "r"(b[1]));
}

// packed f32x2 helpers (sm_100+ base feature)
__device__ __forceinline__ void fma2(uint64_t& d, uint64_t a, uint64_t b) {
    asm("fma.rn.f32x2 %0, %1, %2, %0;" : "+l"(d) : "l"(a), "l"(b));
}
__device__ __forceinline__ uint64_t pack2(float lo, float hi) {
    uint64_t r;
    asm("mov.b64 %0, {%1, %2};" : "=l"(r) : "f"(lo), "f"(hi));
    return r;
}
__device__ __forceinline__ uint64_t mk64(uint32_t lo, uint32_t hi) {
    uint64_t r;
    asm("mov.b64 %0, {%1, %2};" : "=l"(r) : "r"(lo), "r"(hi));
    return r;
}
__device__ __forceinline__ float sum2(uint64_t p) {
    float lo, hi;
    asm("mov.b64 {%0, %1}, %2;" : "=f"(lo), "=f"(hi) : "l"(p));
    return lo + hi;
}

// ---------------- prep: transpose bias+mask to [w][h][j][n] ----------------
__global__ __launch_bounds__(256)
void prep_bm(const float* __restrict__ mask, const float* __restrict__ tbl,
             const int* __restrict__ rel) {
    __shared__ float msm[32][33];
    __shared__ int   rsm[32][33];
    const int w = blockIdx.x >> 4;
    const int tile = blockIdx.x & 15;
    const int nt = tile >> 2, jt = tile & 3;
    const int tx = threadIdx.x & 31, ty = threadIdx.x >> 5;   // ty 0..7

    for (int i = ty; i < 32; i += 8) {
        int n = nt * 32 + i, j = jt * 32 + tx;
        msm[i][tx] = mask[w * 16384 + n * 128 + j];
        rsm[i][tx] = rel[n * 128 + j];
    }
    __syncthreads();
#pragma unroll
    for (int h = 0; h < 8; h++)
        for (int i = ty; i < 32; i += 8) {
            int j = jt * 32 + i;
            g_bm[(((w << 3) + h) << 14) + j * 128 + nt * 32 + tx] =
                tbl[rsm[tx][i] * 8 + h] + msm[tx][i];
        }
}

__global__ void prep_w(const float* __restrict__ Wq, const float* __restrict__ Wkv,
                       const float* __restrict__ Wp) {
    int t = blockIdx.x * blockDim.x + threadIdx.x;   // < 16384
    int lane = t & 31, rest = t >> 5;
    int ks = rest & 7, tile = rest >> 3;
    int lr = lane >> 2, lc = lane & 3;
    int kb = ks * 16 + lc * 2;
    int kk[4] = { kb, kb + 1, kb + 8, kb + 9 };
    if (tile < 48) {
        int n = tile * 8 + lr;
        unsigned short h[4], m[4], l[4];
#pragma unroll
        for (int i = 0; i < 4; i++) {
            int k = kk[i];
            float v = (n < 128) ? Wq[k * 128 + n] * 0.25f : Wkv[k * 256 + (n - 128)];
            split3s(v, h[i], m[i], l[i]);
        }
        int idx = (tile * 8 + ks) * 32 + lane;
        g_Pc_hm[idx] = make_uint4((uint32_t)h[0] | ((uint32_t)h[1] << 16),
                                  (uint32_t)h[2] | ((uint32_t)h[3] << 16),
                                  (uint32_t)m[0] | ((uint32_t)m[1] << 16),
                                  (uint32_t)m[2] | ((uint32_t)m[3] << 16));
        g_Pc_l[idx] = make_uint2((uint32_t)l[0] | ((uint32_t)l[1] << 16),
                                 (uint32_t)l[2] | ((uint32_t)l[3] << 16));
    } else if (tile < 64) {
        int n = (tile - 48) * 8 + lr;
        unsigned short h[4], m[4], l[4];
#pragma unroll
        for (int i = 0; i < 4; i++)
            split3s(Wp[kk[i] * 128 + n], h[i], m[i], l[i]);
        int idx = ((tile - 48) * 8 + ks) * 32 + lane;
        g_Pp_hm[idx] = make_uint4((uint32_t)h[0] | ((uint32_t)h[1] << 16),
                                  (uint32_t)h[2] | ((uint32_t)h[3] << 16),
                                  (uint32_t)m[0] | ((uint32_t)m[1] << 16),
                                  (uint32_t)m[2] | ((uint32_t)m[3] << 16));
    }
}

// ---------------- fully fused attention + projection (512 threads) ----------------
#define SM_XM 32768
#define SM_XL 65536
#define SM_K  98304
#define SM_V  165888
#define ATTN_SMEM 232448
#define PQ 132
#define PK 132
#define PV 130
#define PPX 68
#define SM_PL 34816

__global__ __launch_bounds__(512, 1)
void attn_kernel(const float* __restrict__ x, const float* __restrict__ bp,
                 float* __restrict__ out) {
    extern __shared__ char sm[];
    uint32_t* XH = reinterpret_cast<uint32_t*>(sm);
    uint32_t* XM = reinterpret_cast<uint32_t*>(sm + SM_XM);
    uint32_t* XL = reinterpret_cast<uint32_t*>(sm + SM_XL);
    float* sQ = reinterpret_cast<float*>(sm);
    float* sK = reinterpret_cast<float*>(sm + SM_K);
    float* sV = reinterpret_cast<float*>(sm + SM_V);
    uint32_t* PH = reinterpret_cast<uint32_t*>(sm);            // phase B/C: split xo hi
    uint32_t* PL = reinterpret_cast<uint32_t*>(sm + SM_PL);    // phase B/C: split xo mid

    const int b = blockIdx.x, tid = threadIdx.x;
    const int wid = tid >> 5, lane = tid & 31;

    // stage x -> 3-way bf16 split, swizzled pitch 64
    const float* xb = x + b * 16384;
    for (int p = tid; p < 8192; p += 512) {
        int row = p >> 6, kp = p & 63;
        float2 v = *reinterpret_cast<const float2*>(xb + row * 128 + kp * 2);
        unsigned short h0, m0, l0, h1, m1, l1;
        split3s(v.x, h0, m0, l0);
        split3s(v.y, h1, m1, l1);
        int idx = row * 64 + (kp ^ ((row & 7) << 2));
        XH[idx] = (uint32_t)h0 | ((uint32_t)h1 << 16);
        XM[idx] = (uint32_t)m0 | ((uint32_t)m1 << 16);
        XL[idx] = (uint32_t)l0 | ((uint32_t)l1 << 16);
    }
    __syncthreads();

    // ---- phase A ----
    const int mt = wid & 7, np = wid >> 3, lr = lane >> 2, lc = lane & 3;
    const int sw = lr << 2;
    const int r0 = (mt * 16 + lr) * 64;
    const int r1 = r0 + 8 * 64;

    // mainloop 1: Q (tiles np+2*0..7) + K (tiles np+2*8..15), 6 products each
    float C[16][4];
#pragma unroll
    for (int i = 0; i < 16; i++) { C[i][0] = C[i][1] = C[i][2] = C[i][3] = 0.f; }
#pragma unroll 2
    for (int ks = 0; ks < 8; ks++) {
        const int k0 = (ks * 8 + lc) ^ sw;
        const int k1 = (ks * 8 + lc + 4) ^ sw;
        uint32_t ah[4], am[4], al[4];
        ah[0] = XH[r0 + k0]; ah[1] = XH[r1 + k0]; ah[2] = XH[r0 + k1]; ah[3] = XH[r1 + k1];
        am[0] = XM[r0 + k0]; am[1] = XM[r1 + k0]; am[2] = XM[r0 + k1]; am[3] = XM[r1 + k1];
        al[0] = XL[r0 + k0]; al[1] = XL[r1 + k0]; al[2] = XL[r0 + k1]; al[3] = XL[r1 + k1];
#pragma unroll
        for (int i = 0; i < 16; i++) {
            const int tile = np + 2 * i;
            const int fi = (tile * 8 + ks) * 32 + lane;
            uint4 hm = __ldg(&g_Pc_hm[fi]);
            uint2 l2 = __ldg(&g_Pc_l[fi]);
            uint32_t bh[2] = { hm.x, hm.y };
            uint32_t bm[2] = { hm.z, hm.w };
            uint32_t bl[2] = { l2.x, l2.y };
            hmma(C[i], ah, bh);
            hmma(C[i], am, bh);
            hmma(C[i], ah, bm);
            hmma(C[i], am, bm);
            hmma(C[i], al, bh);
            hmma(C[i], ah, bl);
        }
    }
    // K epilogue (tiles 16..31 -> sK cols 0..127); sK region disjoint from X
#pragma unroll
    for (int i = 8; i < 16; i++) {
        const int col = (np + 2 * i) * 8 + lc * 2 - 128;
        const int row = mt * 16 + lr;
        *reinterpret_cast<float2*>(sK + row * PK + col) = make_float2(C[i][0], C[i][1]);
        *reinterpret_cast<float2*>(sK + (row + 8) * PK + col) = make_float2(C[i][2], C[i][3]);
    }

    // mainloop 2: V (tiles np+2*(16..23)), 3 products
    {
        float D[8][4];
#pragma unroll
        for (int t = 0; t < 8; t++) { D[t][0] = D[t][1] = D[t][2] = D[t][3] = 0.f; }
#pragma unroll 2
        for (int ks = 0; ks < 8; ks++) {
            const int k0 = (ks * 8 + lc) ^ sw;
            const int k1 = (ks * 8 + lc + 4) ^ sw;
            uint32_t ah[4], am[4];
            ah[0] = XH[r0 + k0]; ah[1] = XH[r1 + k0]; ah[2] = XH[r0 + k1]; ah[3] = XH[r1 + k1];
            am[0] = XM[r0 + k0]; am[1] = XM[r1 + k0]; am[2] = XM[r0 + k1]; am[3] = XM[r1 + k1];
#pragma unroll
            for (int t = 0; t < 8; t++) {
                const int tile = np + 2 * (16 + t);
                const int fi = (tile * 8 + ks) * 32 + lane;
                uint4 hm = __ldg(&g_Pc_hm[fi]);
                uint32_t bh[2] = { hm.x, hm.y };
                uint32_t bm[2] = { hm.z, hm.w };
                hmma(D[t], ah, bh);
                hmma(D[t], am, bh);
                hmma(D[t], ah, bm);
            }
        }
#pragma unroll
        for (int t = 0; t < 8; t++) {
            const int col = (np + 2 * (16 + t)) * 8 + lc * 2 - 256;
            const int row = mt * 16 + lr;
            *reinterpret_cast<float2*>(sV + row * PV + col) = make_float2(D[t][0], D[t][1]);
            *reinterpret_cast<float2*>(sV + (row + 8) * PV + col) = make_float2(D[t][2], D[t][3]);
        }
    }
    __syncthreads();     // all X reads complete before Q overlays X
#pragma unroll
    for (int i = 0; i < 8; i++) {
        const int col = (np + 2 * i) * 8 + lc * 2;
        const int row = mt * 16 + lr;
        *reinterpret_cast<float2*>(sQ + row * PQ + col) = make_float2(C[i][0], C[i][1]);
        *reinterpret_cast<float2*>(sQ + (row + 8) * PQ + col) = make_float2(C[i][2], C[i][3]);
    }
    __syncthreads();

    // ---- phase B: rows-per-lane (2 consecutive rows), K broadcast, no shuffles ----
    {
        const int h = wid >> 1, c0 = h * 16;
        const int n0 = (wid & 1) * 64 + 2 * lane;  // row A
        const int n1 = n0 + 1;                      // row B
        const float* bmt = g_bm + ((((b & 63) << 3) + h) << 14);   // [j][n]

        uint64_t q0[8], q1[8];
        {
            const uint4* qa = reinterpret_cast<const uint4*>(sQ + n0 * PQ + c0);
            const uint4* qb = reinterpret_cast<const uint4*>(sQ + n1 * PQ + c0);
#pragma unroll
            for (int u = 0; u < 4; u++) {
                uint4 a = qa[u], bq = qb[u];
                q0[2 * u] = mk64(a.x, a.y);  q0[2 * u + 1] = mk64(a.z, a.w);
                q1[2 * u] = mk64(bq.x, bq.y); q1[2 * u + 1] = mk64(bq.z, bq.w);
            }
        }
        __syncthreads();   // all q reads done before any epilogue PH/PL write (sQ overlay)

        float m1a = -3e38f, m2a = -3e38f, za = 0.f;
        float m1b = -3e38f, m2b = -3e38f, zb = 0.f;
        int i1a = 0, i2a = 0, i1b = 0, i2b = 0;

#pragma unroll 4
        for (int j = 0; j < 128; j++) {
            const uint4* kr4 = reinterpret_cast<const uint4*>(sK + j * PK + c0);
            uint64_t k2[8];
#pragma unroll
            for (int u = 0; u < 4; u++) {
                uint4 kv = kr4[u];    // LDS.128 broadcast (same addr all lanes)
                k2[2 * u] = mk64(kv.x, kv.y);
                k2[2 * u + 1] = mk64(kv.z, kv.w);
            }
            float2 bm2 = __ldg(reinterpret_cast<const float2*>(bmt + j * 128 + n0));

            uint64_t pa = pack2(bm2.x, 0.f), pb = pack2(bm2.y, 0.f);
#pragma unroll
            for (int u = 0; u < 8; u++) { fma2(pa, q0[u], k2[u]); fma2(pb, q1[u], k2[u]); }
            float sa = sum2(pa), sb = sum2(pb);

            { bool g1 = sa > m1a, g2 = sa > m2a;
              float om = m1a; int oi = i1a;
              m2a = g1 ? om : (g2 ? sa : m2a); i2a = g1 ? oi : (g2 ? j : i2a);
              m1a = g1 ? sa : om;              i1a = g1 ? j : oi; }
            { bool g1 = sb > m1b, g2 = sb > m2b;
              float om = m1b; int oi = i1b;
              m2b = g1 ? om : (g2 ? sb : m2b); i2b = g1 ? oi : (g2 ? j : i2b);
              m1b = g1 ? sb : om;              i1b = g1 ? j : oi; }
            za += __expf(sa);
            zb += __expf(sb);
        }

        // epilogue: weighted V rows -> split bf16 hi/mid directly into PH/PL (smem)
#pragma unroll
        for (int r = 0; r < 2; r++) {
            const int n = r ? n1 : n0;
            const float z = r ? zb : za;
            const float w1 = __expf((r ? m1b : m1a)) / z;
            const float w2 = __expf((r ? m2b : m2a)) / z;
            const float* v1 = sV + (r ? i1b : i1a) * PV + c0;
            const float* v2 = sV + (r ? i2b : i2a) * PV + c0;
            const int base = n * PPX + h * 8;
#pragma unroll
            for (int u = 0; u < 8; u++) {
                float2 a = *reinterpret_cast<const float2*>(v1 + 2 * u);
                float2 c = *reinterpret_cast<const float2*>(v2 + 2 * u);
                float ox = fmaf(w1, a.x, w2 * c.x);
                float oy = fmaf(w1, a.y, w2 * c.y);
                unsigned short hx, mx, hy, my;
                split2s(ox, hx, mx);
                split2s(oy, hy, my);
                PH[base + u] = (uint32_t)hx | ((uint32_t)hy << 16);
                PL[base + u] = (uint32_t)mx | ((uint32_t)my << 16);
            }
        }
    }
    __syncthreads();   // PH/PL complete before cross-warp reads

    // ---- phase C: output projection from smem PH/PL ----
    {
        const int arow = (mt * 16 + lr) * PPX;
        float D[8][4];
#pragma unroll
        for (int t = 0; t < 8; t++) { D[t][0] = D[t][1] = D[t][2] = D[t][3] = 0.f; }
#pragma unroll 2
        for (int ks = 0; ks < 8; ks++) {
            const int ai = arow + ks * 8 + lc;
            uint32_t ah[4], al[4];
            ah[0] = PH[ai];     ah[1] = PH[ai + 8 * PPX];
            ah[2] = PH[ai + 4]; ah[3] = PH[ai + 8 * PPX + 4];
            al[0] = PL[ai];     al[1] = PL[ai + 8 * PPX];
            al[2] = PL[ai + 4]; al[3] = PL[ai + 8 * PPX + 4];
#pragma unroll
            for (int t = 0; t < 8; t++) {
                const int tile = np + 2 * t;
                const int fi = (tile * 8 + ks) * 32 + lane;
                uint4 hm = __ldg(&g_Pp_hm[fi]);
                uint32_t bh[2] = { hm.x, hm.y };
                uint32_t bm[2] = { hm.z, hm.w };
                hmma(D[t], ah, bh);
                hmma(D[t], ah, bm);
                hmma(D[t], al, bh);
            }
        }
        float* outB = out + (b << 14);
#pragma unroll
        for (int t = 0; t < 8; t++) {
            const int col = (np + 2 * t) * 8 + lc * 2;
            const int row = mt * 16 + lr;
            const float b0 = __ldg(bp + col), b1 = __ldg(bp + col + 1);
            *reinterpret_cast<float2*>(outB + row * 128 + col) = make_float2(D[t][0] + b0, D[t][1] + b1);
            *reinterpret_cast<float2*>(outB + (row + 8) * 128 + col) = make_float2(D[t][2] + b0, D[t][3] + b1);
        }
    }
}

// ---------------------------------------------------------------------------
extern "C" void kernel_launch(void* const* d_in, const int* in_sizes, int n_in,
                              void* d_out, int out_size) {
    const float* x    = (const float*)d_in[0];
    const float* mask = (const float*)d_in[1];
    const float* Wq   = (const float*)d_in[2];
    const float* Wkv  = (const float*)d_in[3];
    const float* Wp   = (const float*)d_in[4];
    const float* bp   = (const float*)d_in[5];
    const float* tbl  = (const float*)d_in[6];
    const int*   rel  = (const int*)d_in[7];
    float* out = (float*)d_out;

    prep_w<<<32, 512>>>(Wq, Wkv, Wp);
    prep_bm<<<1024, 256>>>(mask, tbl, rel);

    cudaFuncSetAttribute(attn_kernel, cudaFuncAttributeMaxDynamicSharedMemorySize, ATTN_SMEM);
    attn_kernel<<<B_TOT, 512, ATTN_SMEM>>>(x, bp, out);
}